// round 14
// baseline (speedup 1.0000x reference)
#include <cuda_runtime.h>
#include <cstdint>

#define NB 2
#define NV 1024
#define NF 2048
#define NC 3
#define NH 128
#define NW 128
#define TS 16
#define TLX (NW / TS)      // 8 tiles in x
#define TLY (NH / TS)      // 8 tiles in y
#define NT  (TLX * TLY)    // 64 tiles per batch
#define SEG 16             // face-window split per tile
#define WIN (NF / SEG)     // 128 faces per window == blockDim

#define FTINY  ((float)1.1754943508222875e-35)            // finfo(f32).tiny * 1000
#define FINF   ((float)(3.4028234663852886e38 * 0.001))   // finfo(f32).max * 0.001
#define FLOWER ((float)(3.4028234663852886e38 * 0.0001))  // finfo(f32).max * 0.0001

// Persistent scratch. Zero-initialized at module load; the kernel restores the
// all-zero state before exiting, so every graph replay sees a clean slate.
__device__ unsigned long long g_scr[NB * NH * NW];    // ~packed(depthKey,faceIdx); 0 = empty
__device__ unsigned int g_tick[NB * NT];              // per-tile completion tickets

// ---- exact-rounding helpers (match XLA's non-contracted mul/add) ----
__device__ __forceinline__ float f_mul(float a, float b) { return __fmul_rn(a, b); }
__device__ __forceinline__ float f_add(float a, float b) { return __fadd_rn(a, b); }
__device__ __forceinline__ float f_sub(float a, float b) { return __fsub_rn(a, b); }
__device__ __forceinline__ float plane3(float a, float x, float b, float y, float c) {
    return f_add(f_add(f_mul(a, x), f_mul(b, y)), c);
}

// Orderable key for fp32
__device__ __forceinline__ unsigned int fkey(float f) {
    unsigned int u = __float_as_uint(f);
    return (u & 0x80000000u) ? ~u : (u | 0x80000000u);
}
__device__ __forceinline__ float fkey_inv(unsigned int k) {
    unsigned int u = (k & 0x80000000u) ? (k ^ 0x80000000u) : ~k;
    return __uint_as_float(u);
}

__device__ __forceinline__ void bary_coeffs(
    float x0, float x1, float x2, float y0, float y1, float y2,
    float& l0x, float& l0y, float& l0c,
    float& l1x, float& l1y, float& l1c,
    float& l2x, float& l2y, float& l2c)
{
    float det = f_add(f_mul(f_sub(y1, y2), f_sub(x0, x2)),
                      f_mul(f_sub(x2, x1), f_sub(y0, y2)));
    float s  = (det > 0.0f) ? 1.0f : ((det < 0.0f) ? -1.0f : 0.0f);
    float dd = f_mul(s, fmaxf(fabsf(det), FTINY));
    float inv = __fdiv_rn(1.0f, dd);
    l0x = f_mul(f_sub(y1, y2), inv);
    l0y = f_mul(f_sub(x2, x1), inv);
    l0c = f_sub(f_mul(-l0x, x2), f_mul(l0y, y2));
    l1x = f_mul(f_sub(y2, y0), inv);
    l1y = f_mul(f_sub(x0, x2), inv);
    l1c = f_sub(f_mul(-l1x, x2), f_mul(l1y, y2));
    l2x = f_sub(-l0x, l1x);
    l2y = f_sub(-l0y, l1y);
    l2c = f_sub(f_sub(1.0f, l0c), l1c);
}

// Per-plane, per-quadrant conservative pass test (halfspan 3.5 around quadrant
// center). margin >= 16x the 2^-24 rounding bound of any pixel eval.
// NaN/inf coefficients never reject (comparison false -> keep).
__device__ __forceinline__ unsigned quad_mask(float a, float b, float c,
                                              float tx, float ty) {
    float ab  = fabsf(a) + fabsf(b);
    float off = ab * 3.5f + (ab * 128.0f + fabsf(c)) * 1e-6f;
    unsigned m = 0;
    #pragma unroll
    for (int q = 0; q < 4; q++) {
        float cxq = tx + (float)((q & 1) * 8) + 3.5f;
        float cyq = ty + (float)((q >> 1) * 8) + 3.5f;
        float ub = plane3(a, cxq, b, cyq, c) + off;
        if (!(ub < 0.0f)) m |= (1u << q);
    }
    return m;
}

// ---- single kernel: inline setup + per-quadrant dense record lists + linear
//      eval + last-block shade. Block = 128 threads = one 16x16 tile. Warp w
//      owns the 8x8 quadrant (w&1, w>>1); lane l -> pixel (qx*8+(l&7),
//      qy*8+(l>>3)) and the one 4 rows below.
__global__ void __launch_bounds__(128) k_all(
    const float* __restrict__ pt2d, const float* __restrict__ color,
    const float* __restrict__ pt3d, const float* __restrict__ normal,
    const float* __restrict__ Rm, const float* __restrict__ Tm,
    const int* __restrict__ face, float* __restrict__ out)
{
    __shared__ float4 qA[4][WIN], qB[4][WIN], qC[4][WIN];  // 24 KB dense lists
    __shared__ unsigned short qF[4][WIN];                  // face idx per entry
    __shared__ int s_qcnt[4][4];                           // [warp][quadrant]
    __shared__ unsigned int s_tick;

    int b   = blockIdx.z / SEG;
    int seg = blockIdx.z % SEG;
    int tid = threadIdx.x;
    int w    = tid >> 5;
    int lane = tid & 31;
    unsigned lt = (1u << lane) - 1u;

    int tile = blockIdx.y * TLX + blockIdx.x;
    int tx0 = blockIdx.x * TS, ty0 = blockIdx.y * TS;
    float txf = (float)tx0, tyf = (float)ty0;

    const float* p2 = pt2d + b * 3 * NV;
    const float* p3 = pt3d + b * 3 * NV;
    const float* nbp = normal + b * 3 * NF;
    const float* R = Rm + b * 9;
    const float* T = Tm + b * 3;

    // ---- inline setup + quadrant reject: 1 face per thread ----
    int f = seg * WIN + tid;
    unsigned qm;
    float l0x, l0y, l0c, l1x, l1y, l1c, l2x, l2y, l2c, Dx, Dy, Dc;
    {
        int i0 = __ldg(&face[f]), i1 = __ldg(&face[NF + f]), i2 = __ldg(&face[2 * NF + f]);
        float x0 = __ldg(&p2[i0]),          x1 = __ldg(&p2[i1]),          x2 = __ldg(&p2[i2]);
        float y0 = __ldg(&p2[NV + i0]),     y1 = __ldg(&p2[NV + i1]),     y2 = __ldg(&p2[NV + i2]);
        float z0 = __ldg(&p2[2 * NV + i0]), z1 = __ldg(&p2[2 * NV + i1]), z2 = __ldg(&p2[2 * NV + i2]);

        // norm cull: ((v0 + R^T T) . n) < 0
        float v0x = __ldg(&p3[i0]), v0y = __ldg(&p3[NV + i0]), v0z = __ldg(&p3[2 * NV + i0]);
        float nx = __ldg(&nbp[f]), ny = __ldg(&nbp[NF + f]), nz = __ldg(&nbp[2 * NF + f]);
        float o0 = f_add(f_add(f_mul(R[0], T[0]), f_mul(R[3], T[1])), f_mul(R[6], T[2]));
        float o1 = f_add(f_add(f_mul(R[1], T[0]), f_mul(R[4], T[1])), f_mul(R[7], T[2]));
        float o2 = f_add(f_add(f_mul(R[2], T[0]), f_mul(R[5], T[1])), f_mul(R[8], T[2]));
        float dotv = f_add(f_add(f_mul(f_add(v0x, o0), nx),
                                 f_mul(f_add(v0y, o1), ny)),
                           f_mul(f_add(v0z, o2), nz));
        bool valid = (dotv < 0.0f) && (fminf(z0, fminf(z1, z2)) > 0.0f);

        bary_coeffs(x0, x1, x2, y0, y1, y2, l0x, l0y, l0c, l1x, l1y, l1c, l2x, l2y, l2c);

        qm = 0u;
        if (valid) {
            qm = quad_mask(l0x, l0y, l0c, txf, tyf)
               & quad_mask(l1x, l1y, l1c, txf, tyf)
               & quad_mask(l2x, l2y, l2c, txf, tyf);
        }
        Dx = f_add(f_add(f_mul(z0, l0x), f_mul(z1, l1x)), f_mul(z2, l2x));
        Dy = f_add(f_add(f_mul(z0, l0y), f_mul(z1, l1y)), f_mul(z2, l2y));
        Dc = f_add(f_add(f_mul(z0, l0c), f_mul(z1, l1c)), f_mul(z2, l2c));
    }

    // ---- deterministic compaction into per-quadrant dense lists ----
    // (no atomics; entry order = warp-order x lane-order = ascending f)
    unsigned qb0 = __ballot_sync(0xFFFFFFFFu, qm & 1u);
    unsigned qb1 = __ballot_sync(0xFFFFFFFFu, qm & 2u);
    unsigned qb2 = __ballot_sync(0xFFFFFFFFu, qm & 4u);
    unsigned qb3 = __ballot_sync(0xFFFFFFFFu, qm & 8u);
    if (lane == 0) {
        s_qcnt[w][0] = __popc(qb0);
        s_qcnt[w][1] = __popc(qb1);
        s_qcnt[w][2] = __popc(qb2);
        s_qcnt[w][3] = __popc(qb3);
    }
    __syncthreads();

    if (qm != 0u) {
        float4 rA = make_float4(l0x, l0y, l0c, l1x);
        float4 rB = make_float4(l1y, l1c, l2x, l2y);
        float4 rC = make_float4(l2c, Dx,  Dy,  Dc);
        unsigned qb[4] = {qb0, qb1, qb2, qb3};
        #pragma unroll
        for (int q = 0; q < 4; q++) {
            if (qm & (1u << q)) {
                int qoff = 0;
                #pragma unroll
                for (int ww = 0; ww < 4; ww++) if (ww < w) qoff += s_qcnt[ww][q];
                qoff += __popc(qb[q] & lt);
                qA[q][qoff] = rA;
                qB[q][qoff] = rB;
                qC[q][qoff] = rC;
                qF[q][qoff] = (unsigned short)f;
            }
        }
    }
    __syncthreads();

    int mq = s_qcnt[0][w] + s_qcnt[1][w] + s_qcnt[2][w] + s_qcnt[3][w];

    int x   = tx0 + (w & 1) * 8 + (lane & 7);
    int y0p = ty0 + (w >> 1) * 8 + (lane >> 3);  // rows 0..3 of quadrant
    float xf  = (float)x;
    float yf0 = (float)y0p;
    float yf1 = (float)(y0p + 4);

    // Strict '<' + ascending-f list order == argmin first-index tie-break.
    // NaN d fails '<' -> never wins (== reference's where(isnan, INF)).
    float bd0 = FINF, bd1 = FINF;
    int   bj0 = 0,    bj1 = 0;

    const float4* pA = qA[w];
    const float4* pB = qB[w];
    const float4* pC = qC[w];

    #pragma unroll 2
    for (int j = 0; j < mq; j++) {
        float4 A  = pA[j];
        float4 Bq = pB[j];
        float4 Cq = pC[j];

        // shared a*x across the two pixels (CSE-legal: identical rounded op)
        float ax0 = f_mul(A.x,  xf);
        float ax1 = f_mul(A.w,  xf);
        float ax2 = f_mul(Bq.z, xf);
        float axd = f_mul(Cq.y, xf);

        {   // pixel (x, y0p)
            float l0 = f_add(f_add(ax0, f_mul(A.y,  yf0)), A.z);
            float l1 = f_add(f_add(ax1, f_mul(Bq.x, yf0)), Bq.y);
            float l2 = f_add(f_add(ax2, f_mul(Bq.w, yf0)), Cq.x);
            float d  = f_add(f_add(axd, f_mul(Cq.z, yf0)), Cq.w);
            bool better = (l0 >= 0.0f) && (l1 >= 0.0f) && (l2 >= 0.0f) && (d < bd0);
            bd0 = better ? d : bd0;
            bj0 = better ? j : bj0;
        }
        {   // pixel (x, y0p+4)
            float l0 = f_add(f_add(ax0, f_mul(A.y,  yf1)), A.z);
            float l1 = f_add(f_add(ax1, f_mul(Bq.x, yf1)), Bq.y);
            float l2 = f_add(f_add(ax2, f_mul(Bq.w, yf1)), Cq.x);
            float d  = f_add(f_add(axd, f_mul(Cq.z, yf1)), Cq.w);
            bool better = (l0 >= 0.0f) && (l1 >= 0.0f) && (l2 >= 0.0f) && (d < bd1);
            bd1 = better ? d : bd1;
            bj1 = better ? j : bj1;
        }
    }

    // publish: min over key == max over ~key; 0 is the neutral "empty" element,
    // so the zero-initialized (and self-cleaned) g_scr needs no init pass.
    // bd < FINF <=> an update happened (covered d >= FINF loses to empty,
    // matching the reference's all-INF argmin corner).
    int pix0 = b * NH * NW + y0p * NW + x;
    int pix1 = pix0 + 4 * NW;
    if (bd0 < FINF) {
        unsigned fi = qF[w][bj0];
        unsigned long long k = (((unsigned long long)fkey(bd0)) << 32) | fi;
        atomicMax(&g_scr[pix0], ~k);
    }
    if (bd1 < FINF) {
        unsigned fi = qF[w][bj1];
        unsigned long long k = (((unsigned long long)fkey(bd1)) << 32) | fi;
        atomicMax(&g_scr[pix1], ~k);
    }

    // ---- publication + ticket: last block for this tile shades it ----
    __threadfence();                        // atomics visible before ticket
    __syncthreads();                        // whole block published
    if (tid == 0) s_tick = atomicAdd(&g_tick[b * NT + tile], 1u);
    __syncthreads();
    if (s_tick != SEG - 1) return;

    // last block: all segments' results are fenced + complete
    const unsigned long long KEY0 = ((unsigned long long)fkey(FINF)) << 32;
    const float* cb = color + b * 3 * NV;
    #pragma unroll
    for (int h = 0; h < 2; h++) {
        int pix = h ? pix1 : pix0;
        int yy  = h ? (y0p + 4) : y0p;
        unsigned long long s = *(volatile unsigned long long*)&g_scr[pix];
        *(volatile unsigned long long*)&g_scr[pix] = 0ull;   // self-clean for next replay
        unsigned long long key = (s == 0ull) ? KEY0 : ~s;
        int idx = (int)(key & 0xFFFFFFFFull);
        float depth = fkey_inv((unsigned int)(key >> 32));
        float mk = (depth < FLOWER) ? 1.0f : 0.0f;

        // replicate _shade_one: recompute bary from winner's verts + colors
        int i0 = __ldg(&face[idx]), i1 = __ldg(&face[NF + idx]), i2 = __ldg(&face[2 * NF + idx]);
        float x0 = __ldg(&p2[i0]),      x1 = __ldg(&p2[i1]),      x2 = __ldg(&p2[i2]);
        float ya = __ldg(&p2[NV + i0]), yb = __ldg(&p2[NV + i1]), yc = __ldg(&p2[NV + i2]);

        float m0x, m0y, m0c, m1x, m1y, m1c, m2x, m2y, m2c;
        bary_coeffs(x0, x1, x2, ya, yb, yc, m0x, m0y, m0c, m1x, m1y, m1c, m2x, m2y, m2c);

        float yfl = (float)yy;
        #pragma unroll
        for (int ch = 0; ch < NC; ch++) {
            float c0 = __ldg(&cb[ch * NV + i0]);
            float c1 = __ldg(&cb[ch * NV + i1]);
            float c2 = __ldg(&cb[ch * NV + i2]);
            float Cx = f_add(f_add(f_mul(c0, m0x), f_mul(c1, m1x)), f_mul(c2, m2x));
            float Cy = f_add(f_add(f_mul(c0, m0y), f_mul(c1, m1y)), f_mul(c2, m2y));
            float Cc = f_add(f_add(f_mul(c0, m0c), f_mul(c1, m1c)), f_mul(c2, m2c));
            float val = f_add(f_add(f_mul(Cx, xf), f_mul(Cy, yfl)), Cc);
            out[((b * NC + ch) * NH + yy) * NW + x] = f_mul(mk, val);
        }
        out[NB * NC * NH * NW + (b * NH + yy) * NW + x] = mk;
    }
    if (tid == 0) g_tick[b * NT + tile] = 0u;   // self-clean ticket
}

extern "C" void kernel_launch(void* const* d_in, const int* in_sizes, int n_in,
                              void* d_out, int out_size)
{
    const float* pt2d   = (const float*)d_in[0];
    const float* color  = (const float*)d_in[1];
    const float* pt3d   = (const float*)d_in[2];
    const float* normal = (const float*)d_in[3];
    const float* Rm     = (const float*)d_in[4];
    const float* Tm     = (const float*)d_in[5];
    const int*   face   = (const int*)d_in[6];
    float* out = (float*)d_out;

    dim3 grid(TLX, TLY, NB * SEG);
    k_all<<<grid, 128>>>(pt2d, color, pt3d, normal, Rm, Tm, face, out);
}

// round 15
// speedup vs baseline: 1.1800x; 1.1800x over previous
#include <cuda_runtime.h>
#include <cstdint>

#define NB 2
#define NV 1024
#define NF 2048
#define NC 3
#define NH 128
#define NW 128
#define TS 16
#define TLX (NW / TS)      // 8 tiles in x
#define TLY (NH / TS)      // 8 tiles in y
#define NT  (TLX * TLY)    // 64 tiles per batch
#define SEG 16             // face-window split per tile
#define WIN (NF / SEG)     // 128 faces per window == blockDim

#define FTINY  ((float)1.1754943508222875e-35)            // finfo(f32).tiny * 1000
#define FINF   ((float)(3.4028234663852886e38 * 0.001))   // finfo(f32).max * 0.001
#define FLOWER ((float)(3.4028234663852886e38 * 0.0001))  // finfo(f32).max * 0.0001

// Persistent scratch. Zero-initialized at module load; the kernel restores the
// all-zero state before exiting, so every graph replay sees a clean slate.
__device__ unsigned long long g_scr[NB * NH * NW];    // ~packed(depthKey,faceIdx); 0 = empty
__device__ unsigned int g_tick[NB * NT];              // per-tile completion tickets

// ---- exact-rounding helpers (match XLA's non-contracted mul/add) ----
__device__ __forceinline__ float f_mul(float a, float b) { return __fmul_rn(a, b); }
__device__ __forceinline__ float f_add(float a, float b) { return __fadd_rn(a, b); }
__device__ __forceinline__ float f_sub(float a, float b) { return __fsub_rn(a, b); }
__device__ __forceinline__ float plane3(float a, float x, float b, float y, float c) {
    return f_add(f_add(f_mul(a, x), f_mul(b, y)), c);
}

// Orderable key for fp32
__device__ __forceinline__ unsigned int fkey(float f) {
    unsigned int u = __float_as_uint(f);
    return (u & 0x80000000u) ? ~u : (u | 0x80000000u);
}
__device__ __forceinline__ float fkey_inv(unsigned int k) {
    unsigned int u = (k & 0x80000000u) ? (k ^ 0x80000000u) : ~k;
    return __uint_as_float(u);
}

__device__ __forceinline__ void bary_coeffs(
    float x0, float x1, float x2, float y0, float y1, float y2,
    float& l0x, float& l0y, float& l0c,
    float& l1x, float& l1y, float& l1c,
    float& l2x, float& l2y, float& l2c)
{
    float det = f_add(f_mul(f_sub(y1, y2), f_sub(x0, x2)),
                      f_mul(f_sub(x2, x1), f_sub(y0, y2)));
    float s  = (det > 0.0f) ? 1.0f : ((det < 0.0f) ? -1.0f : 0.0f);
    float dd = f_mul(s, fmaxf(fabsf(det), FTINY));
    float inv = __fdiv_rn(1.0f, dd);
    l0x = f_mul(f_sub(y1, y2), inv);
    l0y = f_mul(f_sub(x2, x1), inv);
    l0c = f_sub(f_mul(-l0x, x2), f_mul(l0y, y2));
    l1x = f_mul(f_sub(y2, y0), inv);
    l1y = f_mul(f_sub(x0, x2), inv);
    l1c = f_sub(f_mul(-l1x, x2), f_mul(l1y, y2));
    l2x = f_sub(-l0x, l1x);
    l2y = f_sub(-l0y, l1y);
    l2c = f_sub(f_sub(1.0f, l0c), l1c);
}

// Per-plane, per-quadrant conservative pass test (halfspan 3.5 around quadrant
// center). margin >= 16x the 2^-24 rounding bound of any pixel eval.
// NaN/inf coefficients never reject (comparison false -> keep).
__device__ __forceinline__ unsigned quad_mask(float a, float b, float c,
                                              float tx, float ty) {
    float ab  = fabsf(a) + fabsf(b);
    float off = ab * 3.5f + (ab * 128.0f + fabsf(c)) * 1e-6f;
    unsigned m = 0;
    #pragma unroll
    for (int q = 0; q < 4; q++) {
        float cxq = tx + (float)((q & 1) * 8) + 3.5f;
        float cyq = ty + (float)((q >> 1) * 8) + 3.5f;
        float ub = plane3(a, cxq, b, cyq, c) + off;
        if (!(ub < 0.0f)) m |= (1u << q);
    }
    return m;
}

// ---- single kernel: inline setup + per-quadrant compaction + dense eval +
//      last-block shade. Block = 128 threads = one 16x16 tile. Warp w owns the
//      8x8 quadrant (w&1, w>>1); lane l -> pixel (qx*8+(l&7), qy*8+(l>>3)) and
//      the one 4 rows below.
__global__ void __launch_bounds__(128) k_all(
    const float* __restrict__ pt2d, const float* __restrict__ color,
    const float* __restrict__ pt3d, const float* __restrict__ normal,
    const float* __restrict__ Rm, const float* __restrict__ Tm,
    const int* __restrict__ face, float* __restrict__ out)
{
    __shared__ float4 smA[WIN], smB[WIN], smC[WIN];   // 6 KB survivor records
    __shared__ unsigned short sface[WIN];             // face index per record
    __shared__ unsigned short squad[4][WIN];          // per-quadrant record lists
    __shared__ int s_wcnt[4];                         // keep-count per warp
    __shared__ int s_qcnt[4][4];                      // [warp][quadrant] counts
    __shared__ unsigned int s_tick;

    int b   = blockIdx.z / SEG;
    int seg = blockIdx.z % SEG;
    int tid = threadIdx.x;
    int w    = tid >> 5;
    int lane = tid & 31;
    unsigned lt = (1u << lane) - 1u;

    int tile = blockIdx.y * TLX + blockIdx.x;
    int tx0 = blockIdx.x * TS, ty0 = blockIdx.y * TS;
    float txf = (float)tx0, tyf = (float)ty0;

    const float* p2 = pt2d + b * 3 * NV;
    const float* p3 = pt3d + b * 3 * NV;
    const float* nbp = normal + b * 3 * NF;
    const float* R = Rm + b * 9;
    const float* T = Tm + b * 3;

    // ---- inline setup + quadrant reject: 1 face per thread ----
    int f = seg * WIN + tid;
    unsigned qm;
    float l0x, l0y, l0c, l1x, l1y, l1c, l2x, l2y, l2c, Dx, Dy, Dc;
    {
        int i0 = __ldg(&face[f]), i1 = __ldg(&face[NF + f]), i2 = __ldg(&face[2 * NF + f]);
        float x0 = __ldg(&p2[i0]),          x1 = __ldg(&p2[i1]),          x2 = __ldg(&p2[i2]);
        float y0 = __ldg(&p2[NV + i0]),     y1 = __ldg(&p2[NV + i1]),     y2 = __ldg(&p2[NV + i2]);
        float z0 = __ldg(&p2[2 * NV + i0]), z1 = __ldg(&p2[2 * NV + i1]), z2 = __ldg(&p2[2 * NV + i2]);

        // norm cull: ((v0 + R^T T) . n) < 0
        float v0x = __ldg(&p3[i0]), v0y = __ldg(&p3[NV + i0]), v0z = __ldg(&p3[2 * NV + i0]);
        float nx = __ldg(&nbp[f]), ny = __ldg(&nbp[NF + f]), nz = __ldg(&nbp[2 * NF + f]);
        float o0 = f_add(f_add(f_mul(R[0], T[0]), f_mul(R[3], T[1])), f_mul(R[6], T[2]));
        float o1 = f_add(f_add(f_mul(R[1], T[0]), f_mul(R[4], T[1])), f_mul(R[7], T[2]));
        float o2 = f_add(f_add(f_mul(R[2], T[0]), f_mul(R[5], T[1])), f_mul(R[8], T[2]));
        float dotv = f_add(f_add(f_mul(f_add(v0x, o0), nx),
                                 f_mul(f_add(v0y, o1), ny)),
                           f_mul(f_add(v0z, o2), nz));
        bool valid = (dotv < 0.0f) && (fminf(z0, fminf(z1, z2)) > 0.0f);

        bary_coeffs(x0, x1, x2, y0, y1, y2, l0x, l0y, l0c, l1x, l1y, l1c, l2x, l2y, l2c);

        qm = 0u;
        if (valid) {
            qm = quad_mask(l0x, l0y, l0c, txf, tyf)
               & quad_mask(l1x, l1y, l1c, txf, tyf)
               & quad_mask(l2x, l2y, l2c, txf, tyf);
        }
        Dx = f_add(f_add(f_mul(z0, l0x), f_mul(z1, l1x)), f_mul(z2, l2x));
        Dy = f_add(f_add(f_mul(z0, l0y), f_mul(z1, l1y)), f_mul(z2, l2y));
        Dc = f_add(f_add(f_mul(z0, l0c), f_mul(z1, l1c)), f_mul(z2, l2c));
    }

    // ---- deterministic two-level compaction (no atomics; order = ascending f) ----
    bool keep = (qm != 0u);
    unsigned km = __ballot_sync(0xFFFFFFFFu, keep);
    unsigned qb0 = __ballot_sync(0xFFFFFFFFu, qm & 1u);
    unsigned qb1 = __ballot_sync(0xFFFFFFFFu, qm & 2u);
    unsigned qb2 = __ballot_sync(0xFFFFFFFFu, qm & 4u);
    unsigned qb3 = __ballot_sync(0xFFFFFFFFu, qm & 8u);
    if (lane == 0) {
        s_wcnt[w] = __popc(km);
        s_qcnt[w][0] = __popc(qb0);
        s_qcnt[w][1] = __popc(qb1);
        s_qcnt[w][2] = __popc(qb2);
        s_qcnt[w][3] = __popc(qb3);
    }
    __syncthreads();

    if (keep) {
        int woff = 0;
        #pragma unroll
        for (int ww = 0; ww < 4; ww++) if (ww < w) woff += s_wcnt[ww];
        int p = woff + __popc(km & lt);
        smA[p] = make_float4(l0x, l0y, l0c, l1x);
        smB[p] = make_float4(l1y, l1c, l2x, l2y);
        smC[p] = make_float4(l2c, Dx,  Dy,  Dc);
        sface[p] = (unsigned short)f;
        unsigned qb[4] = {qb0, qb1, qb2, qb3};
        #pragma unroll
        for (int q = 0; q < 4; q++) {
            if (qm & (1u << q)) {
                int qoff = 0;
                #pragma unroll
                for (int ww = 0; ww < 4; ww++) if (ww < w) qoff += s_qcnt[ww][q];
                qoff += __popc(qb[q] & lt);
                squad[q][qoff] = (unsigned short)p;
            }
        }
    }
    __syncthreads();

    int mq = s_qcnt[0][w] + s_qcnt[1][w] + s_qcnt[2][w] + s_qcnt[3][w];

    int x  = tx0 + (w & 1) * 8 + (lane & 7);
    int y0p = ty0 + (w >> 1) * 8 + (lane >> 3);  // rows 0..3 of quadrant
    float xf  = (float)x;
    float yf0 = (float)y0p;
    float yf1 = (float)(y0p + 4);

    // Strict '<' + ascending-f list order == argmin first-index tie-break.
    // NaN d fails '<' -> never wins (== reference's where(isnan, INF)).
    float bd0 = FINF, bd1 = FINF;
    int   bj0 = 0,    bj1 = 0;

    const unsigned short* plist = squad[w];

    #pragma unroll 2
    for (int j = 0; j < mq; j++) {
        int p = plist[j];
        float4 A  = smA[p];
        float4 Bq = smB[p];
        float4 Cq = smC[p];

        // shared a*x across the two pixels (CSE-legal: identical rounded op)
        float ax0 = f_mul(A.x,  xf);
        float ax1 = f_mul(A.w,  xf);
        float ax2 = f_mul(Bq.z, xf);
        float axd = f_mul(Cq.y, xf);

        {   // pixel (x, y0p)
            float l0 = f_add(f_add(ax0, f_mul(A.y,  yf0)), A.z);
            float l1 = f_add(f_add(ax1, f_mul(Bq.x, yf0)), Bq.y);
            float l2 = f_add(f_add(ax2, f_mul(Bq.w, yf0)), Cq.x);
            float d  = f_add(f_add(axd, f_mul(Cq.z, yf0)), Cq.w);
            bool better = (l0 >= 0.0f) && (l1 >= 0.0f) && (l2 >= 0.0f) && (d < bd0);
            bd0 = better ? d : bd0;
            bj0 = better ? j : bj0;
        }
        {   // pixel (x, y0p+4)
            float l0 = f_add(f_add(ax0, f_mul(A.y,  yf1)), A.z);
            float l1 = f_add(f_add(ax1, f_mul(Bq.x, yf1)), Bq.y);
            float l2 = f_add(f_add(ax2, f_mul(Bq.w, yf1)), Cq.x);
            float d  = f_add(f_add(axd, f_mul(Cq.z, yf1)), Cq.w);
            bool better = (l0 >= 0.0f) && (l1 >= 0.0f) && (l2 >= 0.0f) && (d < bd1);
            bd1 = better ? d : bd1;
            bj1 = better ? j : bj1;
        }
    }

    // publish: min over key == max over ~key; 0 is the neutral "empty" element,
    // so the zero-initialized (and self-cleaned) g_scr needs no init pass.
    // bd < FINF <=> an update happened (covered d >= FINF loses to empty,
    // matching the reference's all-INF argmin corner).
    int pix0 = b * NH * NW + y0p * NW + x;
    int pix1 = pix0 + 4 * NW;
    if (bd0 < FINF) {
        unsigned fi = sface[plist[bj0]];
        unsigned long long k = (((unsigned long long)fkey(bd0)) << 32) | fi;
        atomicMax(&g_scr[pix0], ~k);
    }
    if (bd1 < FINF) {
        unsigned fi = sface[plist[bj1]];
        unsigned long long k = (((unsigned long long)fkey(bd1)) << 32) | fi;
        atomicMax(&g_scr[pix1], ~k);
    }

    // ---- publication + ticket: last block for this tile shades it ----
    __threadfence();                        // atomics visible before ticket
    __syncthreads();                        // whole block published
    if (tid == 0) s_tick = atomicAdd(&g_tick[b * NT + tile], 1u);
    __syncthreads();
    if (s_tick != SEG - 1) return;

    // last block: all segments' results are fenced + complete
    const unsigned long long KEY0 = ((unsigned long long)fkey(FINF)) << 32;
    const float* cb = color + b * 3 * NV;
    #pragma unroll
    for (int h = 0; h < 2; h++) {
        int pix = h ? pix1 : pix0;
        int yy  = h ? (y0p + 4) : y0p;
        unsigned long long s = *(volatile unsigned long long*)&g_scr[pix];
        *(volatile unsigned long long*)&g_scr[pix] = 0ull;   // self-clean for next replay
        unsigned long long key = (s == 0ull) ? KEY0 : ~s;
        int idx = (int)(key & 0xFFFFFFFFull);
        float depth = fkey_inv((unsigned int)(key >> 32));
        float mk = (depth < FLOWER) ? 1.0f : 0.0f;

        // replicate _shade_one: recompute bary from winner's verts + colors
        int i0 = __ldg(&face[idx]), i1 = __ldg(&face[NF + idx]), i2 = __ldg(&face[2 * NF + idx]);
        float x0 = __ldg(&p2[i0]),      x1 = __ldg(&p2[i1]),      x2 = __ldg(&p2[i2]);
        float ya = __ldg(&p2[NV + i0]), yb = __ldg(&p2[NV + i1]), yc = __ldg(&p2[NV + i2]);

        float m0x, m0y, m0c, m1x, m1y, m1c, m2x, m2y, m2c;
        bary_coeffs(x0, x1, x2, ya, yb, yc, m0x, m0y, m0c, m1x, m1y, m1c, m2x, m2y, m2c);

        float yfl = (float)yy;
        #pragma unroll
        for (int ch = 0; ch < NC; ch++) {
            float c0 = __ldg(&cb[ch * NV + i0]);
            float c1 = __ldg(&cb[ch * NV + i1]);
            float c2 = __ldg(&cb[ch * NV + i2]);
            float Cx = f_add(f_add(f_mul(c0, m0x), f_mul(c1, m1x)), f_mul(c2, m2x));
            float Cy = f_add(f_add(f_mul(c0, m0y), f_mul(c1, m1y)), f_mul(c2, m2y));
            float Cc = f_add(f_add(f_mul(c0, m0c), f_mul(c1, m1c)), f_mul(c2, m2c));
            float val = f_add(f_add(f_mul(Cx, xf), f_mul(Cy, yfl)), Cc);
            out[((b * NC + ch) * NH + yy) * NW + x] = f_mul(mk, val);
        }
        out[NB * NC * NH * NW + (b * NH + yy) * NW + x] = mk;
    }
    if (tid == 0) g_tick[b * NT + tile] = 0u;   // self-clean ticket
}

extern "C" void kernel_launch(void* const* d_in, const int* in_sizes, int n_in,
                              void* d_out, int out_size)
{
    const float* pt2d   = (const float*)d_in[0];
    const float* color  = (const float*)d_in[1];
    const float* pt3d   = (const float*)d_in[2];
    const float* normal = (const float*)d_in[3];
    const float* Rm     = (const float*)d_in[4];
    const float* Tm     = (const float*)d_in[5];
    const int*   face   = (const int*)d_in[6];
    float* out = (float*)d_out;

    dim3 grid(TLX, TLY, NB * SEG);
    k_all<<<grid, 128>>>(pt2d, color, pt3d, normal, Rm, Tm, face, out);
}